// round 5
// baseline (speedup 1.0000x reference)
#include <cuda_runtime.h>
#include <math.h>

#define NCTA 128
#define NTHR 256
// dynamic smem: xS0(32*33 f4) + xS1(32*33 f4) + wS(96*32 f4) = 5184 float4
#define SMEM_F4 5184
#define SMEM_BYTES (SMEM_F4 * 16)

typedef unsigned long long u64;

// ---------------- packed f32x2 FMA (sm_103a) ----------------
__device__ __forceinline__ u64 fma2(u64 a, u64 b, u64 c) {
    u64 d;
    asm("fma.rn.f32x2 %0, %1, %2, %3;" : "=l"(d) : "l"(a), "l"(b), "l"(c));
    return d;
}
__device__ __forceinline__ float hsum(u64 v) {
    union { u64 u; float f[2]; } x; x.u = v;
    return x.f[0] + x.f[1];
}
__device__ __forceinline__ float sigm(float x) { return 1.f / (1.f + expf(-x)); }
__device__ __forceinline__ float softplusf(float x) {
    return fmaxf(x, 0.f) + log1pf(expf(-fabsf(x)));
}

// ---------------- persistent state ----------------
__device__ float g_emb[64 * 1024];
__device__ float g_det[2][64 * 1024];
__device__ float g_h1[64 * 512];
__device__ float g_hq[64 * 512];
__device__ float g_stoch[64 * 32];

__device__ unsigned g_cnt;
__device__ volatile unsigned g_gen;

// sense-reversing grid barrier; all 128 CTAs guaranteed co-resident.
__device__ __forceinline__ void gbar() {
    __threadfence();              // release: order this thread's global writes
    __syncthreads();
    if (threadIdx.x == 0) {
        unsigned gen = g_gen;
        if (atomicAdd(&g_cnt, 1u) == NCTA - 1) {
            g_cnt = 0;
            __threadfence();
            g_gen = gen + 1;
        } else {
            while (g_gen == gen) { }
        }
        __threadfence();          // acquire: fence.gpu -> CCTL.IVALL (flush L1)
    }
    __syncthreads();
}

extern "C" __global__ void __launch_bounds__(NTHR, 1)
rssm_kernel(const float* __restrict__ obs,   // [64][256][1024]
            const float* __restrict__ act,   // [64][256][64]
            const float* __restrict__ nzp,   // [64][256][32]
            const float* __restrict__ nzq,   // [64][256][32]
            const float* __restrict__ Wsa, const float* __restrict__ bsa,   // [1024][96]
            const float* __restrict__ Wih, const float* __restrict__ bih,   // [3072][1024]
            const float* __restrict__ Whh, const float* __restrict__ bhh,   // [3072][1024]
            const float* __restrict__ Wp1, const float* __restrict__ bp1,   // [512][1024]
            const float* __restrict__ Wp2, const float* __restrict__ bp2,   // [64][512]
            const float* __restrict__ Wq1, const float* __restrict__ bq1,   // [512][2048]
            const float* __restrict__ Wq2, const float* __restrict__ bq2,   // [64][512]
            float* __restrict__ out)         // [64][256][1216]
{
    extern __shared__ float4 S[];
    float4* xS0 = S;            // 32*33
    float4* xS1 = S + 1056;     // 32*33
    float4* wS  = S + 2112;     // 96*32

    const int tid  = threadIdx.x;
    const int lane = tid & 31;
    const int wrp  = tid >> 5;
    const int bg   = blockIdx.x >> 6;   // 0/1 : batch half
    const int cg   = blockIdx.x & 63;   // column group
    const int b    = bg * 32 + lane;

    // ---- init state ----
    for (int i = blockIdx.x * NTHR + tid; i < 64 * 1024; i += NCTA * NTHR)
        g_det[0][i] = 0.f;
    for (int i = blockIdx.x * NTHR + tid; i < 64 * 32; i += NCTA * NTHR)
        g_stoch[i] = 0.f;
    gbar();

    for (int t = 0; t < 256; ++t) {
        const int p = t & 1;
        const float* detP = g_det[p];
        float*       detN = g_det[p ^ 1];

        // ================= phase 1: emb = relu([stoch|act] @ Wsa^T + bsa) =================
        {
            // stage x: [32 rows][24 f4] (96 floats), padded stride 25
            for (int i = tid; i < 32 * 24; i += NTHR) {
                int row = i / 24, k4 = i - row * 24;
                float4 v;
                if (k4 < 8)
                    v = *(const float4*)(g_stoch + (bg * 32 + row) * 32 + k4 * 4);
                else
                    v = *(const float4*)(act + ((size_t)(bg * 32 + row) * 256 + t) * 64 + (k4 - 8) * 4);
                xS0[row * 25 + k4] = v;
            }
            __syncthreads();
            const int c0 = cg * 16 + wrp * 2;
            u64 a0 = 0, a1 = 0;
            const ulonglong2* xr = (const ulonglong2*)(xS0 + lane * 25);
            const ulonglong2* w0 = (const ulonglong2*)(Wsa + (size_t)c0 * 96);
            const ulonglong2* w1 = (const ulonglong2*)(Wsa + (size_t)(c0 + 1) * 96);
            #pragma unroll 6
            for (int k4 = 0; k4 < 24; ++k4) {
                ulonglong2 x = xr[k4];
                ulonglong2 u = w0[k4], v = w1[k4];
                a0 = fma2(x.x, u.x, a0); a0 = fma2(x.y, u.y, a0);
                a1 = fma2(x.x, v.x, a1); a1 = fma2(x.y, v.y, a1);
            }
            g_emb[(size_t)b * 1024 + c0]     = fmaxf(hsum(a0) + bsa[c0], 0.f);
            g_emb[(size_t)b * 1024 + c0 + 1] = fmaxf(hsum(a1) + bsa[c0 + 1], 0.f);
        }
        gbar();

        // ================= phase 2: GRU -> new deter =================
        {
            const int d0 = cg * 16;
            const int cA = d0 + wrp * 2;
            u64 acc[2][6];
            #pragma unroll
            for (int i = 0; i < 2; ++i)
                #pragma unroll
                for (int j = 0; j < 6; ++j) acc[i][j] = 0ull;

            for (int kc = 0; kc < 8; ++kc) {
                // stage x: emb + detP, 2 x [32][32] f4, padded stride 33
                for (int i = tid; i < 2048; i += NTHR) {
                    int mat = i >> 10, row = (i >> 5) & 31, k4 = i & 31;
                    const float* src = mat ? detP : g_emb;
                    float4 v = *(const float4*)(src + (size_t)(bg * 32 + row) * 1024 + kc * 128 + k4 * 4);
                    (mat ? xS1 : xS0)[row * 33 + k4] = v;
                }
                // stage w: 96 rows (16 cols x 6 gate-mats) x 32 f4
                for (int i = tid; i < 3072; i += NTHR) {
                    int r = i >> 5, k4 = i & 31;
                    int j = r / 6, m = r - j * 6;
                    const float* srow = (m < 3)
                        ? (Wih + (size_t)(d0 + j + 1024 * m) * 1024)
                        : (Whh + (size_t)(d0 + j + 1024 * (m - 3)) * 1024);
                    wS[r * 32 + k4] = *(const float4*)(srow + kc * 128 + k4 * 4);
                }
                __syncthreads();
                const ulonglong2* xe = (const ulonglong2*)(xS0 + lane * 33);
                const ulonglong2* xd = (const ulonglong2*)(xS1 + lane * 33);
                const ulonglong2* wA = (const ulonglong2*)(wS + (wrp * 2) * 6 * 32);
                #pragma unroll 4
                for (int k4 = 0; k4 < 32; ++k4) {
                    ulonglong2 e = xe[k4];
                    ulonglong2 d = xd[k4];
                    #pragma unroll
                    for (int cc = 0; cc < 2; ++cc) {
                        const ulonglong2* wr = wA + cc * 6 * 32 + k4;
                        #pragma unroll
                        for (int m = 0; m < 6; ++m) {
                            ulonglong2 wv = wr[m * 32];
                            u64 x0 = (m < 3) ? e.x : d.x;
                            u64 x1 = (m < 3) ? e.y : d.y;
                            acc[cc][m] = fma2(wv.x, x0, acc[cc][m]);
                            acc[cc][m] = fma2(wv.y, x1, acc[cc][m]);
                        }
                    }
                }
                __syncthreads();
            }
            #pragma unroll
            for (int cc = 0; cc < 2; ++cc) {
                int c = cA + cc;
                float ir = hsum(acc[cc][0]) + bih[c];
                float iz = hsum(acc[cc][1]) + bih[c + 1024];
                float in = hsum(acc[cc][2]) + bih[c + 2048];
                float hr = hsum(acc[cc][3]) + bhh[c];
                float hz = hsum(acc[cc][4]) + bhh[c + 1024];
                float hn = hsum(acc[cc][5]) + bhh[c + 2048];
                float r  = sigm(ir + hr);
                float z  = sigm(iz + hz);
                float n  = tanhf(in + r * hn);
                float hp = detP[(size_t)b * 1024 + c];
                float hw = (1.f - z) * n + z * hp;
                detN[(size_t)b * 1024 + c] = hw;
                out[((size_t)b * 256 + t) * 1216 + c] = hw;
            }
        }
        gbar();

        // ================= phase 3: h1 = relu(deter@Wp1^T+bp1), hq = relu([deter|obs]@Wq1^T+bq1) =====
        {
            const bool isQ = (cg >= 32);
            const int  c0  = (isQ ? (cg - 32) : cg) * 16;
            const int  cT  = c0 + wrp * 2;
            u64 a0 = 0, a1 = 0;
            const int nch = isQ ? 16 : 8;
            for (int kc = 0; kc < nch; ++kc) {
                for (int i = tid; i < 1024; i += NTHR) {
                    int row = i >> 5, k4 = i & 31;
                    float4 v;
                    if (isQ && kc >= 8)
                        v = *(const float4*)(obs + ((size_t)(bg * 32 + row) * 256 + t) * 1024 + (kc - 8) * 128 + k4 * 4);
                    else
                        v = *(const float4*)(detN + (size_t)(bg * 32 + row) * 1024 + kc * 128 + k4 * 4);
                    xS0[row * 33 + k4] = v;
                }
                for (int i = tid; i < 512; i += NTHR) {
                    int r = i >> 5, k4 = i & 31;
                    const float* srow = isQ ? (Wq1 + (size_t)(c0 + r) * 2048)
                                            : (Wp1 + (size_t)(c0 + r) * 1024);
                    wS[r * 32 + k4] = *(const float4*)(srow + kc * 128 + k4 * 4);
                }
                __syncthreads();
                const ulonglong2* xr = (const ulonglong2*)(xS0 + lane * 33);
                const ulonglong2* w0 = (const ulonglong2*)(wS + (wrp * 2) * 32);
                const ulonglong2* w1 = (const ulonglong2*)(wS + (wrp * 2 + 1) * 32);
                #pragma unroll 4
                for (int k4 = 0; k4 < 32; ++k4) {
                    ulonglong2 x = xr[k4];
                    ulonglong2 u = w0[k4], v = w1[k4];
                    a0 = fma2(x.x, u.x, a0); a0 = fma2(x.y, u.y, a0);
                    a1 = fma2(x.x, v.x, a1); a1 = fma2(x.y, v.y, a1);
                }
                __syncthreads();
            }
            float*       dst = isQ ? g_hq : g_h1;
            const float* bb  = isQ ? bq1 : bp1;
            dst[(size_t)b * 512 + cT]     = fmaxf(hsum(a0) + bb[cT], 0.f);
            dst[(size_t)b * 512 + cT + 1] = fmaxf(hsum(a1) + bb[cT + 1], 0.f);
        }
        gbar();

        // ================= phase 4: heads, stochastic outputs, next stoch =================
        {
            const int gw = blockIdx.x * 8 + wrp;    // 0..1023
            #pragma unroll
            for (int i = 0; i < 4; ++i) {
                int pi    = gw * 4 + i;             // 0..4095
                int which = pi & 1;                 // 0 = prior, 1 = posterior
                int s     = (pi >> 1) & 31;
                int bb_   = pi >> 6;
                const float* h  = (which ? g_hq : g_h1) + (size_t)bb_ * 512;
                const float* W2 = which ? Wq2 : Wp2;
                const ulonglong2* xm = (const ulonglong2*)(h + lane * 16);
                const ulonglong2* wm = (const ulonglong2*)(W2 + (size_t)s * 512 + lane * 16);
                const ulonglong2* ws = (const ulonglong2*)(W2 + (size_t)(s + 32) * 512 + lane * 16);
                u64 am = 0, asd = 0;
                #pragma unroll
                for (int q = 0; q < 4; ++q) {
                    ulonglong2 x = xm[q];
                    ulonglong2 u = wm[q], v = ws[q];
                    am  = fma2(x.x, u.x, am);  am  = fma2(x.y, u.y, am);
                    asd = fma2(x.x, v.x, asd); asd = fma2(x.y, v.y, asd);
                }
                float sm = hsum(am), ss = hsum(asd);
                #pragma unroll
                for (int o = 16; o; o >>= 1) {
                    sm += __shfl_xor_sync(0xffffffffu, sm, o);
                    ss += __shfl_xor_sync(0xffffffffu, ss, o);
                }
                if (lane == 0) {
                    const float* b2   = which ? bq2 : bp2;
                    float mean = sm + b2[s];
                    float stdv = softplusf(ss + b2[s + 32]) + 1e-5f;
                    const float* nz = which ? nzq : nzp;
                    float e  = nz[((size_t)bb_ * 256 + t) * 32 + s];
                    float st = mean + stdv * e;
                    size_t base = ((size_t)bb_ * 256 + t) * 1216 + 1024 + which * 96;
                    out[base + s]      = mean;
                    out[base + 32 + s] = stdv;
                    out[base + 64 + s] = st;
                    if (which) g_stoch[bb_ * 32 + s] = st;
                }
            }
        }
        gbar();
    }
}

extern "C" void kernel_launch(void* const* d_in, const int* in_sizes, int n_in,
                              void* d_out, int out_size) {
    (void)in_sizes; (void)n_in; (void)out_size;
    cudaFuncSetAttribute((const void*)rssm_kernel,
                         cudaFuncAttributeMaxDynamicSharedMemorySize, SMEM_BYTES);
    rssm_kernel<<<NCTA, NTHR, SMEM_BYTES>>>(
        (const float*)d_in[0],  (const float*)d_in[1],
        (const float*)d_in[2],  (const float*)d_in[3],
        (const float*)d_in[4],  (const float*)d_in[5],
        (const float*)d_in[6],  (const float*)d_in[7],
        (const float*)d_in[8],  (const float*)d_in[9],
        (const float*)d_in[10], (const float*)d_in[11],
        (const float*)d_in[12], (const float*)d_in[13],
        (const float*)d_in[14], (const float*)d_in[15],
        (const float*)d_in[16], (const float*)d_in[17],
        (float*)d_out);
}

// round 6
// speedup vs baseline: 1.0070x; 1.0070x over previous
#include <cuda_runtime.h>
#include <math.h>

#define NCTA 128
#define NTHR 256
// dynamic smem: xS0(32*33 f4) + xS1(32*33 f4) + wS(96*32 f4) = 5184 float4
#define SMEM_F4 5184
#define SMEM_BYTES (SMEM_F4 * 16)

typedef unsigned long long u64;

// ---------------- packed f32x2 FMA (sm_103a) ----------------
__device__ __forceinline__ u64 fma2(u64 a, u64 b, u64 c) {
    u64 d;
    asm("fma.rn.f32x2 %0, %1, %2, %3;" : "=l"(d) : "l"(a), "l"(b), "l"(c));
    return d;
}
__device__ __forceinline__ float hsum(u64 v) {
    union { u64 u; float f[2]; } x; x.u = v;
    return x.f[0] + x.f[1];
}
__device__ __forceinline__ float sigm(float x) { return 1.f / (1.f + expf(-x)); }
__device__ __forceinline__ float softplusf(float x) {
    return fmaxf(x, 0.f) + log1pf(expf(-fabsf(x)));
}

// ---------------- persistent state ----------------
__device__ float g_emb[64 * 1024];
__device__ float g_det[2][64 * 1024];
__device__ float g_h1[64 * 512];
__device__ float g_hq[64 * 512];
__device__ float g_stoch[64 * 32];

__device__ unsigned g_cnt;
__device__ volatile unsigned g_gen;

// sense-reversing grid barrier; all 128 CTAs guaranteed co-resident.
__device__ __forceinline__ void gbar() {
    __threadfence();              // release: order this thread's global writes
    __syncthreads();
    if (threadIdx.x == 0) {
        unsigned gen = g_gen;
        if (atomicAdd(&g_cnt, 1u) == NCTA - 1) {
            g_cnt = 0;
            __threadfence();
            g_gen = gen + 1;
        } else {
            while (g_gen == gen) { }
        }
        __threadfence();          // acquire: fence.gpu -> CCTL.IVALL (flush L1)
    }
    __syncthreads();
}

extern "C" __global__ void __launch_bounds__(NTHR, 1)
rssm_kernel(const float* __restrict__ obs,   // [64][256][1024]
            const float* __restrict__ act,   // [64][256][64]
            const float* __restrict__ nzp,   // [64][256][32]
            const float* __restrict__ nzq,   // [64][256][32]
            const float* __restrict__ Wsa, const float* __restrict__ bsa,   // [1024][96]
            const float* __restrict__ Wih, const float* __restrict__ bih,   // [3072][1024]
            const float* __restrict__ Whh, const float* __restrict__ bhh,   // [3072][1024]
            const float* __restrict__ Wp1, const float* __restrict__ bp1,   // [512][1024]
            const float* __restrict__ Wp2, const float* __restrict__ bp2,   // [64][512]
            const float* __restrict__ Wq1, const float* __restrict__ bq1,   // [512][2048]
            const float* __restrict__ Wq2, const float* __restrict__ bq2,   // [64][512]
            float* __restrict__ out)         // [64][256][1216]
{
    extern __shared__ float4 S[];
    float4* xS0 = S;            // 32*33
    float4* xS1 = S + 1056;     // 32*33
    float4* wS  = S + 2112;     // 96*32

    const int tid  = threadIdx.x;
    const int lane = tid & 31;
    const int wrp  = tid >> 5;
    const int bg   = blockIdx.x >> 6;   // 0/1 : batch half
    const int cg   = blockIdx.x & 63;   // column group
    const int b    = bg * 32 + lane;

    // ---- init state ----
    for (int i = blockIdx.x * NTHR + tid; i < 64 * 1024; i += NCTA * NTHR)
        g_det[0][i] = 0.f;
    for (int i = blockIdx.x * NTHR + tid; i < 64 * 32; i += NCTA * NTHR)
        g_stoch[i] = 0.f;
    gbar();

    for (int t = 0; t < 256; ++t) {
        const int p = t & 1;
        const float* detP = g_det[p];
        float*       detN = g_det[p ^ 1];

        // ================= phase 1: emb = relu([stoch|act] @ Wsa^T + bsa) =================
        {
            // stage x: [32 rows][24 f4] (96 floats), padded stride 25
            for (int i = tid; i < 32 * 24; i += NTHR) {
                int row = i / 24, k4 = i - row * 24;
                float4 v;
                if (k4 < 8)
                    v = *(const float4*)(g_stoch + (bg * 32 + row) * 32 + k4 * 4);
                else
                    v = *(const float4*)(act + ((size_t)(bg * 32 + row) * 256 + t) * 64 + (k4 - 8) * 4);
                xS0[row * 25 + k4] = v;
            }
            __syncthreads();
            const int c0 = cg * 16 + wrp * 2;
            u64 a0 = 0, a1 = 0;
            const ulonglong2* xr = (const ulonglong2*)(xS0 + lane * 25);
            const ulonglong2* w0 = (const ulonglong2*)(Wsa + (size_t)c0 * 96);
            const ulonglong2* w1 = (const ulonglong2*)(Wsa + (size_t)(c0 + 1) * 96);
            #pragma unroll 6
            for (int k4 = 0; k4 < 24; ++k4) {
                ulonglong2 x = xr[k4];
                ulonglong2 u = w0[k4], v = w1[k4];
                a0 = fma2(x.x, u.x, a0); a0 = fma2(x.y, u.y, a0);
                a1 = fma2(x.x, v.x, a1); a1 = fma2(x.y, v.y, a1);
            }
            g_emb[(size_t)b * 1024 + c0]     = fmaxf(hsum(a0) + bsa[c0], 0.f);
            g_emb[(size_t)b * 1024 + c0 + 1] = fmaxf(hsum(a1) + bsa[c0 + 1], 0.f);
        }
        gbar();

        // ================= phase 2: GRU -> new deter =================
        {
            const int d0 = cg * 16;
            const int cA = d0 + wrp * 2;
            u64 acc[2][6];
            #pragma unroll
            for (int i = 0; i < 2; ++i)
                #pragma unroll
                for (int j = 0; j < 6; ++j) acc[i][j] = 0ull;

            for (int kc = 0; kc < 8; ++kc) {
                // stage x: emb + detP, 2 x [32][32] f4, padded stride 33
                for (int i = tid; i < 2048; i += NTHR) {
                    int mat = i >> 10, row = (i >> 5) & 31, k4 = i & 31;
                    const float* src = mat ? detP : g_emb;
                    float4 v = *(const float4*)(src + (size_t)(bg * 32 + row) * 1024 + kc * 128 + k4 * 4);
                    (mat ? xS1 : xS0)[row * 33 + k4] = v;
                }
                // stage w: 96 rows (16 cols x 6 gate-mats) x 32 f4
                for (int i = tid; i < 3072; i += NTHR) {
                    int r = i >> 5, k4 = i & 31;
                    int j = r / 6, m = r - j * 6;
                    const float* srow = (m < 3)
                        ? (Wih + (size_t)(d0 + j + 1024 * m) * 1024)
                        : (Whh + (size_t)(d0 + j + 1024 * (m - 3)) * 1024);
                    wS[r * 32 + k4] = *(const float4*)(srow + kc * 128 + k4 * 4);
                }
                __syncthreads();
                const ulonglong2* xe = (const ulonglong2*)(xS0 + lane * 33);
                const ulonglong2* xd = (const ulonglong2*)(xS1 + lane * 33);
                const ulonglong2* wA = (const ulonglong2*)(wS + (wrp * 2) * 6 * 32);
                #pragma unroll 4
                for (int k4 = 0; k4 < 32; ++k4) {
                    ulonglong2 e = xe[k4];
                    ulonglong2 d = xd[k4];
                    #pragma unroll
                    for (int cc = 0; cc < 2; ++cc) {
                        const ulonglong2* wr = wA + cc * 6 * 32 + k4;
                        #pragma unroll
                        for (int m = 0; m < 6; ++m) {
                            ulonglong2 wv = wr[m * 32];
                            u64 x0 = (m < 3) ? e.x : d.x;
                            u64 x1 = (m < 3) ? e.y : d.y;
                            acc[cc][m] = fma2(wv.x, x0, acc[cc][m]);
                            acc[cc][m] = fma2(wv.y, x1, acc[cc][m]);
                        }
                    }
                }
                __syncthreads();
            }
            #pragma unroll
            for (int cc = 0; cc < 2; ++cc) {
                int c = cA + cc;
                float ir = hsum(acc[cc][0]) + bih[c];
                float iz = hsum(acc[cc][1]) + bih[c + 1024];
                float in = hsum(acc[cc][2]) + bih[c + 2048];
                float hr = hsum(acc[cc][3]) + bhh[c];
                float hz = hsum(acc[cc][4]) + bhh[c + 1024];
                float hn = hsum(acc[cc][5]) + bhh[c + 2048];
                float r  = sigm(ir + hr);
                float z  = sigm(iz + hz);
                float n  = tanhf(in + r * hn);
                float hp = detP[(size_t)b * 1024 + c];
                float hw = (1.f - z) * n + z * hp;
                detN[(size_t)b * 1024 + c] = hw;
                out[((size_t)b * 256 + t) * 1216 + c] = hw;
            }
        }
        gbar();

        // ================= phase 3: h1 = relu(deter@Wp1^T+bp1), hq = relu([deter|obs]@Wq1^T+bq1) =====
        {
            const bool isQ = (cg >= 32);
            const int  c0  = (isQ ? (cg - 32) : cg) * 16;
            const int  cT  = c0 + wrp * 2;
            u64 a0 = 0, a1 = 0;
            const int nch = isQ ? 16 : 8;
            for (int kc = 0; kc < nch; ++kc) {
                for (int i = tid; i < 1024; i += NTHR) {
                    int row = i >> 5, k4 = i & 31;
                    float4 v;
                    if (isQ && kc >= 8)
                        v = *(const float4*)(obs + ((size_t)(bg * 32 + row) * 256 + t) * 1024 + (kc - 8) * 128 + k4 * 4);
                    else
                        v = *(const float4*)(detN + (size_t)(bg * 32 + row) * 1024 + kc * 128 + k4 * 4);
                    xS0[row * 33 + k4] = v;
                }
                for (int i = tid; i < 512; i += NTHR) {
                    int r = i >> 5, k4 = i & 31;
                    const float* srow = isQ ? (Wq1 + (size_t)(c0 + r) * 2048)
                                            : (Wp1 + (size_t)(c0 + r) * 1024);
                    wS[r * 32 + k4] = *(const float4*)(srow + kc * 128 + k4 * 4);
                }
                __syncthreads();
                const ulonglong2* xr = (const ulonglong2*)(xS0 + lane * 33);
                const ulonglong2* w0 = (const ulonglong2*)(wS + (wrp * 2) * 32);
                const ulonglong2* w1 = (const ulonglong2*)(wS + (wrp * 2 + 1) * 32);
                #pragma unroll 4
                for (int k4 = 0; k4 < 32; ++k4) {
                    ulonglong2 x = xr[k4];
                    ulonglong2 u = w0[k4], v = w1[k4];
                    a0 = fma2(x.x, u.x, a0); a0 = fma2(x.y, u.y, a0);
                    a1 = fma2(x.x, v.x, a1); a1 = fma2(x.y, v.y, a1);
                }
                __syncthreads();
            }
            float*       dst = isQ ? g_hq : g_h1;
            const float* bb  = isQ ? bq1 : bp1;
            dst[(size_t)b * 512 + cT]     = fmaxf(hsum(a0) + bb[cT], 0.f);
            dst[(size_t)b * 512 + cT + 1] = fmaxf(hsum(a1) + bb[cT + 1], 0.f);
        }
        gbar();

        // ================= phase 4: heads, stochastic outputs, next stoch =================
        {
            const int gw = blockIdx.x * 8 + wrp;    // 0..1023
            #pragma unroll
            for (int i = 0; i < 4; ++i) {
                int pi    = gw * 4 + i;             // 0..4095
                int which = pi & 1;                 // 0 = prior, 1 = posterior
                int s     = (pi >> 1) & 31;
                int bb_   = pi >> 6;
                const float* h  = (which ? g_hq : g_h1) + (size_t)bb_ * 512;
                const float* W2 = which ? Wq2 : Wp2;
                const ulonglong2* xm = (const ulonglong2*)(h + lane * 16);
                const ulonglong2* wm = (const ulonglong2*)(W2 + (size_t)s * 512 + lane * 16);
                const ulonglong2* ws = (const ulonglong2*)(W2 + (size_t)(s + 32) * 512 + lane * 16);
                u64 am = 0, asd = 0;
                #pragma unroll
                for (int q = 0; q < 4; ++q) {
                    ulonglong2 x = xm[q];
                    ulonglong2 u = wm[q], v = ws[q];
                    am  = fma2(x.x, u.x, am);  am  = fma2(x.y, u.y, am);
                    asd = fma2(x.x, v.x, asd); asd = fma2(x.y, v.y, asd);
                }
                float sm = hsum(am), ss = hsum(asd);
                #pragma unroll
                for (int o = 16; o; o >>= 1) {
                    sm += __shfl_xor_sync(0xffffffffu, sm, o);
                    ss += __shfl_xor_sync(0xffffffffu, ss, o);
                }
                if (lane == 0) {
                    const float* b2   = which ? bq2 : bp2;
                    float mean = sm + b2[s];
                    float stdv = softplusf(ss + b2[s + 32]) + 1e-5f;
                    const float* nz = which ? nzq : nzp;
                    float e  = nz[((size_t)bb_ * 256 + t) * 32 + s];
                    float st = mean + stdv * e;
                    size_t base = ((size_t)bb_ * 256 + t) * 1216 + 1024 + which * 96;
                    out[base + s]      = mean;
                    out[base + 32 + s] = stdv;
                    out[base + 64 + s] = st;
                    if (which) g_stoch[bb_ * 32 + s] = st;
                }
            }
        }
        gbar();
    }
}

extern "C" void kernel_launch(void* const* d_in, const int* in_sizes, int n_in,
                              void* d_out, int out_size) {
    (void)in_sizes; (void)n_in; (void)out_size;
    cudaFuncSetAttribute((const void*)rssm_kernel,
                         cudaFuncAttributeMaxDynamicSharedMemorySize, SMEM_BYTES);
    rssm_kernel<<<NCTA, NTHR, SMEM_BYTES>>>(
        (const float*)d_in[0],  (const float*)d_in[1],
        (const float*)d_in[2],  (const float*)d_in[3],
        (const float*)d_in[4],  (const float*)d_in[5],
        (const float*)d_in[6],  (const float*)d_in[7],
        (const float*)d_in[8],  (const float*)d_in[9],
        (const float*)d_in[10], (const float*)d_in[11],
        (const float*)d_in[12], (const float*)d_in[13],
        (const float*)d_in[14], (const float*)d_in[15],
        (const float*)d_in[16], (const float*)d_in[17],
        (float*)d_out);
}

// round 7
// speedup vs baseline: 1.2950x; 1.2860x over previous
#include <cuda_runtime.h>
#include <math.h>

#define NCTA 128
#define NTHR 512
#define SMEM_BYTES ((12288 + 2048) * 16)   // 229376 B: wG(196.6KB) + xB(32KB)

typedef unsigned long long u64;
typedef ulonglong2 ull2;

// ---------------- packed f32x2 FMA (sm_103a) ----------------
__device__ __forceinline__ u64 fma2(u64 a, u64 b, u64 c) {
    u64 d;
    asm("fma.rn.f32x2 %0, %1, %2, %3;" : "=l"(d) : "l"(a), "l"(b), "l"(c));
    return d;
}
__device__ __forceinline__ float hsum(u64 v) {
    union { u64 u; float f[2]; } x; x.u = v;
    return x.f[0] + x.f[1];
}
__device__ __forceinline__ float sigm(float x) { return 1.f / (1.f + expf(-x)); }
__device__ __forceinline__ float softplusf(float x) {
    return fmaxf(x, 0.f) + log1pf(expf(-fabsf(x)));
}
__device__ __forceinline__ void cpa16(float4* dst, const void* src) {
    unsigned s = (unsigned)__cvta_generic_to_shared(dst);
    asm volatile("cp.async.cg.shared.global [%0], [%1], 16;" :: "r"(s), "l"(src));
}
#define CP_COMMIT() asm volatile("cp.async.commit_group;" ::: "memory")
#define CP_WAIT1()  asm volatile("cp.async.wait_group 1;" ::: "memory")
#define CP_WAIT0()  asm volatile("cp.async.wait_group 0;" ::: "memory")

// ---------------- persistent state ----------------
__device__ float g_emb[64 * 1024];
__device__ float g_det[2][64 * 1024];
__device__ float g_h1[64 * 512];
__device__ float g_hq[64 * 512];
__device__ float g_stoch[64 * 32];
__device__ float g_obsq[64 * 256 * 512];   // obs @ Wq1[:,1024:]^T + bq1
__device__ unsigned g_cnt;
__device__ volatile unsigned g_gen;

// sense-reversing grid barrier; 128 CTAs, 1/SM, all co-resident
__device__ __forceinline__ void gbar() {
    __threadfence();
    __syncthreads();
    if (threadIdx.x == 0) {
        unsigned gen = g_gen;
        if (atomicAdd(&g_cnt, 1u) == NCTA - 1) {
            g_cnt = 0;
            __threadfence();
            g_gen = gen + 1;
        } else {
            while (g_gen == gen) { }
        }
        __threadfence();
    }
    __syncthreads();
}

// ======== pre-pass: g_obsq[r][c] = obs[r]·Wq1[c][1024:] + bq1[c], r=(b,t) ========
__global__ void __launch_bounds__(256)
obsq_kernel(const float* __restrict__ obs, const float* __restrict__ Wq1,
            const float* __restrict__ bq1) {
    extern __shared__ float4 S[];           // x: 64*17=1088 f4, w: 128*16=2048 f4
    const int tid = threadIdx.x, lane = tid & 31, wrp = tid >> 5;
    const int rt = blockIdx.x >> 2, ct = blockIdx.x & 3;
    const int r0 = rt * 64, c0 = ct * 128;
    const int rh = wrp >> 2, cgq = wrp & 3;

    u64 acc[32];
    #pragma unroll
    for (int j = 0; j < 32; ++j) acc[j] = 0ull;

    for (int c = 0; c < 16; ++c) {
        for (int i = tid; i < 1024; i += 256) {
            int row = i >> 4, k4 = i & 15;
            S[row * 17 + k4] = *(const float4*)(obs + (size_t)(r0 + row) * 1024 + c * 64 + k4 * 4);
        }
        for (int i = tid; i < 2048; i += 256) {
            int col = i >> 4, k4 = i & 15;
            S[1088 + col * 16 + k4] =
                *(const float4*)(Wq1 + (size_t)(c0 + col) * 2048 + 1024 + c * 64 + k4 * 4);
        }
        __syncthreads();
        const ull2* xr = (const ull2*)(S + (rh * 32 + lane) * 17);
        const ull2* wb = (const ull2*)(S + 1088 + (cgq * 32) * 16);
        for (int k4 = 0; k4 < 16; ++k4) {
            ull2 x = xr[k4];
            #pragma unroll
            for (int j = 0; j < 32; ++j) {
                ull2 w = wb[j * 16 + k4];
                acc[j] = fma2(w.x, x.x, acc[j]);
                acc[j] = fma2(w.y, x.y, acc[j]);
            }
        }
        __syncthreads();
    }
    int r = r0 + rh * 32 + lane;
    #pragma unroll
    for (int j = 0; j < 32; ++j) {
        int col = c0 + cgq * 32 + j;
        g_obsq[(size_t)r * 512 + col] = hsum(acc[j]) + bq1[col];
    }
}

// ======== persistent rollout ========
__global__ void __launch_bounds__(NTHR, 1)
rssm_kernel(const float* __restrict__ obs,   const float* __restrict__ act,
            const float* __restrict__ nzp,   const float* __restrict__ nzq,
            const float* __restrict__ Wsa, const float* __restrict__ bsa,
            const float* __restrict__ Wih, const float* __restrict__ bih,
            const float* __restrict__ Whh, const float* __restrict__ bhh,
            const float* __restrict__ Wp1, const float* __restrict__ bp1,
            const float* __restrict__ Wp2, const float* __restrict__ bp2,
            const float* __restrict__ Wq1, const float* __restrict__ bq1,
            const float* __restrict__ Wq2, const float* __restrict__ bq2,
            float* __restrict__ out)         // [64][256][1216]
{
    extern __shared__ float4 S[];
    float4* wG = S;                 // 12288 f4: [col 0..7][gate 0..5][256 k4]
    float4* xB = S + 12288;         // 2048 f4 scratch / double buffers

    const int tid  = threadIdx.x;
    const int lane = tid & 31;
    const int wrp  = tid >> 5;
    const int c    = wrp & 7;           // column within CTA's group of 8
    const int rh   = wrp >> 3;          // row half
    const int row  = rh * 32 + lane;    // batch row 0..63
    const int sw   = row & 7;           // xor-swizzle key
    const int c0g  = blockIdx.x * 8;    // GRU/emb column base (8 per CTA)

    // ---- one-time: init state + preload GRU weight slice into smem ----
    for (int i = blockIdx.x * NTHR + tid; i < 64 * 1024; i += NCTA * NTHR)
        g_det[0][i] = 0.f;
    for (int i = blockIdx.x * NTHR + tid; i < 64 * 32; i += NCTA * NTHR)
        g_stoch[i] = 0.f;
    for (int i = tid; i < 12288; i += NTHR) {
        int cm = i >> 8, k4 = i & 255;
        int cc = cm / 6, m = cm - cc * 6;
        const float* srow = (m < 3)
            ? (Wih + (size_t)(c0g + cc + 1024 * m) * 1024)
            : (Whh + (size_t)(c0g + cc + 1024 * (m - 3)) * 1024);
        wG[i] = *(const float4*)(srow + k4 * 4);
    }
    gbar();

    for (int t = 0; t < 256; ++t) {
        const int p = t & 1;
        const float* detP = g_det[p];
        float*       detN = g_det[p ^ 1];

        // ===== phase 1: emb = relu([stoch|act] @ Wsa^T + bsa), K=96 =====
        {
            for (int i = tid; i < 1536; i += NTHR) {      // 64 rows x 24 f4
                int r = i / 24, k4 = i - r * 24;
                float4 v;
                if (k4 < 8)
                    v = __ldcg((const float4*)(g_stoch + r * 32 + k4 * 4));
                else
                    v = *(const float4*)(act + ((size_t)r * 256 + t) * 64 + (k4 - 8) * 4);
                xB[r * 25 + k4] = v;
            }
            __syncthreads();
            const int col = c0g + c;
            u64 a = 0;
            const ull2* xr = (const ull2*)(xB + row * 25);
            const ull2* w0 = (const ull2*)(Wsa + (size_t)col * 96);
            #pragma unroll 6
            for (int k4 = 0; k4 < 24; ++k4) {
                ull2 x = xr[k4], u = w0[k4];
                a = fma2(u.x, x.x, a); a = fma2(u.y, x.y, a);
            }
            g_emb[(size_t)row * 1024 + col] = fmaxf(hsum(a) + bsa[col], 0.f);
        }
        gbar();

        // ===== phase 2: GRU (weights resident in smem, x double-buffered) =====
        {
            float4* buf0 = xB;
            float4* buf1 = xB + 1024;
            u64 acc[6] = {0, 0, 0, 0, 0, 0};

            auto stage = [&](float4* buf, int j) {
                for (int i = tid; i < 1024; i += NTHR) {
                    int mat = i >> 9, rem = i & 511, r = rem >> 3, k4 = rem & 7;
                    const float* src = (mat ? detP : g_emb)
                        + (size_t)r * 1024 + j * 32 + k4 * 4;
                    cpa16(buf + mat * 512 + r * 8 + (k4 ^ (r & 7)), src);
                }
            };
            stage(buf0, 0); CP_COMMIT();
            stage(buf1, 1); CP_COMMIT();

            const float4* wbase = wG + c * 6 * 256;
            for (int j = 0; j < 32; ++j) {
                if (j == 31) CP_WAIT0(); else CP_WAIT1();
                __syncthreads();
                const float4* buf = (j & 1) ? buf1 : buf0;
                #pragma unroll
                for (int k4 = 0; k4 < 8; ++k4) {
                    ull2 e = *(const ull2*)(buf + row * 8 + (k4 ^ sw));
                    ull2 d = *(const ull2*)(buf + 512 + row * 8 + (k4 ^ sw));
                    #pragma unroll
                    for (int m = 0; m < 6; ++m) {
                        ull2 wv = *(const ull2*)(wbase + m * 256 + j * 8 + k4);
                        u64 x0 = (m < 3) ? e.x : d.x;
                        u64 x1 = (m < 3) ? e.y : d.y;
                        acc[m] = fma2(wv.x, x0, acc[m]);
                        acc[m] = fma2(wv.y, x1, acc[m]);
                    }
                }
                __syncthreads();
                if (j < 30) { stage((j & 1) ? buf1 : buf0, j + 2); CP_COMMIT(); }
            }

            const int col = c0g + c;
            float ir = hsum(acc[0]) + bih[col];
            float iz = hsum(acc[1]) + bih[col + 1024];
            float in = hsum(acc[2]) + bih[col + 2048];
            float hr = hsum(acc[3]) + bhh[col];
            float hz = hsum(acc[4]) + bhh[col + 1024];
            float hn = hsum(acc[5]) + bhh[col + 2048];
            float r  = sigm(ir + hr);
            float z  = sigm(iz + hz);
            float n  = tanhf(in + r * hn);
            float hp = detP[(size_t)row * 1024 + col];
            float hw = (1.f - z) * n + z * hp;
            detN[(size_t)row * 1024 + col] = hw;
            out[((size_t)row * 256 + t) * 1216 + col] = hw;
        }
        gbar();

        // ===== phase 3: h1 = relu(det@Wp1^T+bp1) ; hq = relu(det@Wq1[:,:1024]^T + obsq) =====
        {
            const bool isQ = blockIdx.x & 1;
            const int  c0  = (blockIdx.x >> 1) * 8;
            const float* W1 = isQ ? Wq1 : Wp1;
            const size_t K1 = isQ ? 2048 : 1024;
            float4* buf0 = xB;
            float4* buf1 = xB + 1024;
            u64 a = 0;

            auto stage3 = [&](float4* buf, int j) {
                for (int i = tid; i < 512; i += NTHR) {
                    int r = i >> 3, k4 = i & 7;
                    cpa16(buf + r * 8 + (k4 ^ (r & 7)),
                          detN + (size_t)r * 1024 + j * 32 + k4 * 4);
                }
                if (tid < 64) {
                    int cc = tid >> 3, k4 = tid & 7;
                    cpa16(buf + 512 + cc * 8 + k4,
                          W1 + (size_t)(c0 + cc) * K1 + j * 32 + k4 * 4);
                }
            };
            stage3(buf0, 0); CP_COMMIT();
            stage3(buf1, 1); CP_COMMIT();

            for (int j = 0; j < 32; ++j) {
                if (j == 31) CP_WAIT0(); else CP_WAIT1();
                __syncthreads();
                const float4* buf = (j & 1) ? buf1 : buf0;
                #pragma unroll
                for (int k4 = 0; k4 < 8; ++k4) {
                    ull2 x = *(const ull2*)(buf + row * 8 + (k4 ^ sw));
                    ull2 w = *(const ull2*)(buf + 512 + c * 8 + k4);
                    a = fma2(w.x, x.x, a); a = fma2(w.y, x.y, a);
                }
                __syncthreads();
                if (j < 30) { stage3((j & 1) ? buf1 : buf0, j + 2); CP_COMMIT(); }
            }

            const int col = c0 + c;
            float base = isQ ? g_obsq[((size_t)row * 256 + t) * 512 + col] : bp1[col];
            float v = fmaxf(hsum(a) + base, 0.f);
            (isQ ? g_hq : g_h1)[(size_t)row * 512 + col] = v;
        }
        gbar();

        // ===== phase 4: heads (mean/std/stoch), update g_stoch =====
        {
            const int gw = blockIdx.x * 16 + wrp;       // 0..2047
            #pragma unroll
            for (int i = 0; i < 2; ++i) {
                int pi    = gw * 2 + i;                 // 0..4095
                int which = pi & 1;
                int s     = (pi >> 1) & 31;
                int bb    = pi >> 6;
                const float* h  = (which ? g_hq : g_h1) + (size_t)bb * 512;
                const float* W2 = which ? Wq2 : Wp2;
                u64 am = 0, asd = 0;
                #pragma unroll
                for (int q = 0; q < 4; ++q) {
                    float4 xf = __ldcg((const float4*)(h + lane * 16 + q * 4));
                    ull2 x = *(ull2*)&xf;
                    ull2 u = *(const ull2*)(W2 + (size_t)s * 512 + lane * 16 + q * 4);
                    ull2 v = *(const ull2*)(W2 + (size_t)(s + 32) * 512 + lane * 16 + q * 4);
                    am  = fma2(u.x, x.x, am);  am  = fma2(u.y, x.y, am);
                    asd = fma2(v.x, x.x, asd); asd = fma2(v.y, x.y, asd);
                }
                float sm = hsum(am), ss = hsum(asd);
                #pragma unroll
                for (int o = 16; o; o >>= 1) {
                    sm += __shfl_xor_sync(0xffffffffu, sm, o);
                    ss += __shfl_xor_sync(0xffffffffu, ss, o);
                }
                if (lane == 0) {
                    const float* b2 = which ? bq2 : bp2;
                    float mean = sm + b2[s];
                    float stdv = softplusf(ss + b2[s + 32]) + 1e-5f;
                    const float* nz = which ? nzq : nzp;
                    float e  = nz[((size_t)bb * 256 + t) * 32 + s];
                    float st = mean + stdv * e;
                    size_t base = ((size_t)bb * 256 + t) * 1216 + 1024 + which * 96;
                    out[base + s]      = mean;
                    out[base + 32 + s] = stdv;
                    out[base + 64 + s] = st;
                    if (which) g_stoch[bb * 32 + s] = st;
                }
            }
        }
        gbar();
    }
}

extern "C" void kernel_launch(void* const* d_in, const int* in_sizes, int n_in,
                              void* d_out, int out_size) {
    (void)in_sizes; (void)n_in; (void)out_size;
    cudaFuncSetAttribute((const void*)obsq_kernel,
                         cudaFuncAttributeMaxDynamicSharedMemorySize, 50176);
    cudaFuncSetAttribute((const void*)rssm_kernel,
                         cudaFuncAttributeMaxDynamicSharedMemorySize, SMEM_BYTES);
    obsq_kernel<<<1024, 256, 50176>>>(
        (const float*)d_in[0], (const float*)d_in[14], (const float*)d_in[15]);
    rssm_kernel<<<NCTA, NTHR, SMEM_BYTES>>>(
        (const float*)d_in[0],  (const float*)d_in[1],
        (const float*)d_in[2],  (const float*)d_in[3],
        (const float*)d_in[4],  (const float*)d_in[5],
        (const float*)d_in[6],  (const float*)d_in[7],
        (const float*)d_in[8],  (const float*)d_in[9],
        (const float*)d_in[10], (const float*)d_in[11],
        (const float*)d_in[12], (const float*)d_in[13],
        (const float*)d_in[14], (const float*)d_in[15],
        (const float*)d_in[16], (const float*)d_in[17],
        (float*)d_out);
}

// round 8
// speedup vs baseline: 1.6006x; 1.2360x over previous
#include <cuda_runtime.h>
#include <math.h>

#define NCTA 128
#define NTHR 512

// smem (float4 units):
//   wG   [0, 12336)        : 48 gatecols x 257 (GRU weights, resident)
//   xb   [12336, 14384)    : 2 x 1024 chunk buffers (GRU: e 512 + d 512)
//     ph3 overlay: per buf [0..512) x-chunk, [512..584) w-chunk (8x9)
//     ph1 overlay: scratch 64x25 = 1600 f4; wSa 8x25 = 200 f4 at +1600
#define WG_F4   12336
#define SMEM_F4 (WG_F4 + 2048)
#define SMEM_BYTES (SMEM_F4 * 16)   // 230144 <= 232448

typedef unsigned long long u64;
typedef ulonglong2 ull2;

__device__ __forceinline__ u64 fma2(u64 a, u64 b, u64 c) {
    u64 d;
    asm("fma.rn.f32x2 %0, %1, %2, %3;" : "=l"(d) : "l"(a), "l"(b), "l"(c));
    return d;
}
__device__ __forceinline__ float hsum(u64 v) {
    union { u64 u; float f[2]; } x; x.u = v;
    return x.f[0] + x.f[1];
}
__device__ __forceinline__ float sigm(float x) { return 1.f / (1.f + expf(-x)); }
__device__ __forceinline__ float softplusf(float x) {
    return fmaxf(x, 0.f) + log1pf(expf(-fabsf(x)));
}
__device__ __forceinline__ void cpa16(float4* dst, const void* src) {
    unsigned s = (unsigned)__cvta_generic_to_shared(dst);
    asm volatile("cp.async.cg.shared.global [%0], [%1], 16;" :: "r"(s), "l"(src));
}
#define CP_COMMIT() asm volatile("cp.async.commit_group;" ::: "memory")
#define CP_WAIT1()  asm volatile("cp.async.wait_group 1;" ::: "memory")
#define CP_WAIT0()  asm volatile("cp.async.wait_group 0;" ::: "memory")

// ---------------- persistent state ----------------
__device__ float g_emb[64 * 1024];
__device__ float g_det[2][64 * 1024];
__device__ float g_h1[64 * 512];
__device__ float g_hq[64 * 512];
__device__ float g_stoch[64 * 32];
__device__ float g_obsq[64 * 256 * 512];
__device__ unsigned g_cnt;
__device__ volatile unsigned g_gen;

// grid barrier: fence only in thread0 (cumulative), 128 co-resident CTAs
__device__ __forceinline__ void gbar() {
    __syncthreads();
    if (threadIdx.x == 0) {
        __threadfence();
        unsigned gen = g_gen;
        if (atomicAdd(&g_cnt, 1u) == NCTA - 1) {
            g_cnt = 0;
            __threadfence();
            g_gen = gen + 1;
        } else {
            while (g_gen == gen) { }
        }
        __threadfence();
    }
    __syncthreads();
}

// ======== pre-pass: g_obsq[r][c] = obs[r]·Wq1[c][1024:] + bq1[c] ========
__global__ void __launch_bounds__(256)
obsq_kernel(const float* __restrict__ obs, const float* __restrict__ Wq1,
            const float* __restrict__ bq1) {
    extern __shared__ float4 S[];
    const int tid = threadIdx.x, lane = tid & 31, wrp = tid >> 5;
    const int rt = blockIdx.x >> 2, ct = blockIdx.x & 3;
    const int r0 = rt * 64, c0 = ct * 128;
    const int rh = wrp >> 2, cgq = wrp & 3;

    u64 acc[32];
    #pragma unroll
    for (int j = 0; j < 32; ++j) acc[j] = 0ull;

    for (int c = 0; c < 16; ++c) {
        for (int i = tid; i < 1024; i += 256) {
            int row = i >> 4, k4 = i & 15;
            S[row * 17 + k4] = *(const float4*)(obs + (size_t)(r0 + row) * 1024 + c * 64 + k4 * 4);
        }
        for (int i = tid; i < 2048; i += 256) {
            int col = i >> 4, k4 = i & 15;
            S[1088 + col * 16 + k4] =
                *(const float4*)(Wq1 + (size_t)(c0 + col) * 2048 + 1024 + c * 64 + k4 * 4);
        }
        __syncthreads();
        const ull2* xr = (const ull2*)(S + (rh * 32 + lane) * 17);
        const ull2* wb = (const ull2*)(S + 1088 + (cgq * 32) * 16);
        for (int k4 = 0; k4 < 16; ++k4) {
            ull2 x = xr[k4];
            #pragma unroll
            for (int j = 0; j < 32; ++j) {
                ull2 w = wb[j * 16 + k4];
                acc[j] = fma2(w.x, x.x, acc[j]);
                acc[j] = fma2(w.y, x.y, acc[j]);
            }
        }
        __syncthreads();
    }
    int r = r0 + rh * 32 + lane;
    #pragma unroll
    for (int j = 0; j < 32; ++j) {
        int col = c0 + cgq * 32 + j;
        g_obsq[(size_t)r * 512 + col] = hsum(acc[j]) + bq1[col];
    }
}

// ======== persistent rollout ========
__global__ void __launch_bounds__(NTHR, 1)
rssm_kernel(const float* __restrict__ obs,   const float* __restrict__ act,
            const float* __restrict__ nzp,   const float* __restrict__ nzq,
            const float* __restrict__ Wsa, const float* __restrict__ bsa,
            const float* __restrict__ Wih, const float* __restrict__ bih,
            const float* __restrict__ Whh, const float* __restrict__ bhh,
            const float* __restrict__ Wp1, const float* __restrict__ bp1,
            const float* __restrict__ Wp2, const float* __restrict__ bp2,
            const float* __restrict__ Wq1, const float* __restrict__ bq1,
            const float* __restrict__ Wq2, const float* __restrict__ bq2,
            float* __restrict__ out)
{
    extern __shared__ float4 S[];
    float4* wG = S;
    float4* xb = S + WG_F4;

    const int tid  = threadIdx.x;
    const int lane = tid & 31;
    const int wrp  = tid >> 5;
    const int c0g  = blockIdx.x * 8;

    // GRU tiling ids: warp = 16 rows x 2 cols; thread = 2 rows x 3 gates (one matrix)
    const int gw_r = wrp & 3;             // row group (16 rows)
    const int gw_c = wrp >> 2;            // col group (2 cols)
    const int tr   = lane & 7;
    const int tc   = lane >> 3;           // 0..3
    const int gr0  = gw_r * 16 + tr;      // row 0
    const int gr1  = gr0 + 8;             // row 1
    const int gcol = gw_c * 2 + (tc >> 1);           // 0..7 within CTA
    const int gpar = (tc & 1);                        // 0 = i-gates (emb), 1 = h-gates (det)
    // ph3/ph1 tiling: warp = 8 rows x 4 cols; thread = 1 output
    const int pr   = (wrp & 7) * 8 + (lane & 7);      // row 0..63
    const int pc   = (wrp >> 3) * 4 + (lane >> 3);    // col 0..7

    // ---- init: zero state, load GRU weights into smem [gc][257] ----
    for (int i = blockIdx.x * NTHR + tid; i < 64 * 1024; i += NCTA * NTHR)
        g_det[0][i] = 0.f;
    for (int i = blockIdx.x * NTHR + tid; i < 64 * 32; i += NCTA * NTHR)
        g_stoch[i] = 0.f;
    for (int i = tid; i < WG_F4; i += NTHR) {
        int gc = i / 257, k = i - gc * 257;
        if (k < 256) {
            int col = gc / 6, g = gc - col * 6;
            const float* srow = (g < 3)
                ? (Wih + ((size_t)(c0g + col) + 1024 * g) * 1024)
                : (Whh + ((size_t)(c0g + col) + 1024 * (g - 3)) * 1024);
            wG[i] = *(const float4*)(srow + k * 4);
        }
    }
    gbar();

    // GRU per-thread weight bases: 3 gates at gc = gcol*6 + gpar*3 + {0,1,2}
    const float4* wg0 = wG + (gcol * 6 + gpar * 3 + 0) * 257;
    const float4* wg1 = wG + (gcol * 6 + gpar * 3 + 1) * 257;
    const float4* wg2 = wG + (gcol * 6 + gpar * 3 + 2) * 257;

    for (int t = 0; t < 256; ++t) {
        const int p = t & 1;
        const float* detP = g_det[p];
        float*       detN = g_det[p ^ 1];

        // ===== phase 1: emb = relu([stoch|act] @ Wsa^T + bsa) =====
        {
            float4* scr = xb;            // 64 x 25
            float4* wsa = xb + 1600;     // 8 x 25
            for (int i = tid; i < 1536; i += NTHR) {
                int row = i / 24, k4 = i - row * 24;
                const void* src = (k4 < 8)
                    ? (const void*)(g_stoch + row * 32 + k4 * 4)
                    : (const void*)(act + ((size_t)row * 256 + t) * 64 + (k4 - 8) * 4);
                cpa16(scr + row * 25 + k4, src);
            }
            if (tid < 192) {
                int c = tid / 24, k4 = tid - c * 24;
                cpa16(wsa + c * 25 + k4, Wsa + (size_t)(c0g + c) * 96 + k4 * 4);
            }
            CP_COMMIT(); CP_WAIT0();
            __syncthreads();
            u64 a = 0;
            #pragma unroll 6
            for (int k4 = 0; k4 < 24; ++k4) {
                ull2 x = *(const ull2*)(scr + pr * 25 + k4);
                ull2 w = *(const ull2*)(wsa + pc * 25 + k4);
                a = fma2(w.x, x.x, a); a = fma2(w.y, x.y, a);
            }
            g_emb[(size_t)pr * 1024 + c0g + pc] = fmaxf(hsum(a) + bsa[c0g + pc], 0.f);
        }
        gbar();

        // ===== phase 2: GRU =====
        {
            float4* b0 = xb;
            float4* b1 = xb + 1024;
            u64 acc[6] = {0, 0, 0, 0, 0, 0};   // [r01*3 + gate]

            auto stageG = [&](float4* buf, int j) {
                #pragma unroll
                for (int s = 0; s < 2; ++s) {
                    int i = tid + s * 512;
                    int mat = i >> 9, idx = i & 511, row = idx >> 3, k4 = idx & 7;
                    const float* src = (mat ? detP : g_emb)
                        + (size_t)row * 1024 + j * 32 + k4 * 4;
                    cpa16(buf + mat * 512 + row * 8 + (k4 ^ (row & 7)), src);
                }
            };
            stageG(b0, 0); CP_COMMIT();
            stageG(b1, 1); CP_COMMIT();

            const int xbase0 = gpar * 512 + gr0 * 8;
            const int xbase1 = gpar * 512 + gr1 * 8;
            for (int j = 0; j < 32; ++j) {
                if (j == 31) CP_WAIT0(); else CP_WAIT1();
                __syncthreads();
                const float4* buf = (j & 1) ? b1 : b0;
                const float4* w0 = wg0 + j * 8;
                const float4* w1 = wg1 + j * 8;
                const float4* w2 = wg2 + j * 8;
                #pragma unroll
                for (int k4 = 0; k4 < 8; ++k4) {
                    int sk = k4 ^ tr;
                    ull2 x0 = *(const ull2*)(buf + xbase0 + sk);
                    ull2 x1 = *(const ull2*)(buf + xbase1 + sk);
                    ull2 wa = *(const ull2*)(w0 + k4);
                    ull2 wb = *(const ull2*)(w1 + k4);
                    ull2 wc = *(const ull2*)(w2 + k4);
                    acc[0] = fma2(wa.x, x0.x, acc[0]); acc[0] = fma2(wa.y, x0.y, acc[0]);
                    acc[1] = fma2(wb.x, x0.x, acc[1]); acc[1] = fma2(wb.y, x0.y, acc[1]);
                    acc[2] = fma2(wc.x, x0.x, acc[2]); acc[2] = fma2(wc.y, x0.y, acc[2]);
                    acc[3] = fma2(wa.x, x1.x, acc[3]); acc[3] = fma2(wa.y, x1.y, acc[3]);
                    acc[4] = fma2(wb.x, x1.x, acc[4]); acc[4] = fma2(wb.y, x1.y, acc[4]);
                    acc[5] = fma2(wc.x, x1.x, acc[5]); acc[5] = fma2(wc.y, x1.y, acc[5]);
                }
                __syncthreads();
                if (j < 30) { stageG((j & 1) ? b1 : b0, j + 2); CP_COMMIT(); }
            }

            const int col = c0g + gcol;
            const float* bb = gpar ? bhh : bih;
            float s[6];
            #pragma unroll
            for (int r01 = 0; r01 < 2; ++r01)
                #pragma unroll
                for (int m = 0; m < 3; ++m)
                    s[r01 * 3 + m] = hsum(acc[r01 * 3 + m]) + bb[col + 1024 * m];
            float o[6];
            #pragma unroll
            for (int i = 0; i < 6; ++i)
                o[i] = __shfl_xor_sync(0xffffffffu, s[i], 8);
            if (!gpar) {
                #pragma unroll
                for (int r01 = 0; r01 < 2; ++r01) {
                    int row = r01 ? gr1 : gr0;
                    float r  = sigm(s[r01 * 3 + 0] + o[r01 * 3 + 0]);
                    float z  = sigm(s[r01 * 3 + 1] + o[r01 * 3 + 1]);
                    float n  = tanhf(s[r01 * 3 + 2] + r * o[r01 * 3 + 2]);
                    float hp = detP[(size_t)row * 1024 + col];
                    float hw = (1.f - z) * n + z * hp;
                    detN[(size_t)row * 1024 + col] = hw;
                    out[((size_t)row * 256 + t) * 1216 + col] = hw;
                }
            }
        }
        gbar();

        // ===== phase 3: h1 / hq first layers (K=1024 both; obs part precomputed) =====
        {
            const bool isQ = blockIdx.x & 1;
            const int  c0  = (blockIdx.x >> 1) * 8;
            const float* W1 = isQ ? Wq1 : Wp1;
            const size_t K1 = isQ ? 2048 : 1024;
            float4* b0 = xb;
            float4* b1 = xb + 1024;
            u64 a = 0;

            auto stage3 = [&](float4* buf, int j) {
                {
                    int row = tid >> 3, k4 = tid & 7;
                    if (tid < 512)
                        cpa16(buf + row * 8 + (k4 ^ (row & 7)),
                              detN + (size_t)row * 1024 + j * 32 + k4 * 4);
                }
                if (tid < 64) {
                    int c = tid >> 3, k4 = tid & 7;
                    cpa16(buf + 512 + c * 9 + k4,
                          W1 + (size_t)(c0 + c) * K1 + j * 32 + k4 * 4);
                }
            };
            stage3(b0, 0); CP_COMMIT();
            stage3(b1, 1); CP_COMMIT();

            for (int j = 0; j < 32; ++j) {
                if (j == 31) CP_WAIT0(); else CP_WAIT1();
                __syncthreads();
                const float4* buf = (j & 1) ? b1 : b0;
                #pragma unroll
                for (int k4 = 0; k4 < 8; ++k4) {
                    ull2 x = *(const ull2*)(buf + pr * 8 + (k4 ^ (pr & 7)));
                    ull2 w = *(const ull2*)(buf + 512 + pc * 9 + k4);
                    a = fma2(w.x, x.x, a); a = fma2(w.y, x.y, a);
                }
                __syncthreads();
                if (j < 30) { stage3((j & 1) ? b1 : b0, j + 2); CP_COMMIT(); }
            }

            const int col = c0 + pc;
            float base = isQ ? g_obsq[((size_t)pr * 256 + t) * 512 + col] : bp1[col];
            float v = fmaxf(hsum(a) + base, 0.f);
            (isQ ? g_hq : g_h1)[(size_t)pr * 512 + col] = v;
        }
        gbar();

        // ===== phase 4: second-layer heads, stochastic state =====
        {
            const int gw = blockIdx.x * 16 + wrp;       // 0..2047
            #pragma unroll
            for (int i = 0; i < 2; ++i) {
                int pi    = gw * 2 + i;                 // 0..4095
                int which = pi & 1;
                int s     = (pi >> 1) & 31;
                int bb    = pi >> 6;
                const float* h  = (which ? g_hq : g_h1) + (size_t)bb * 512;
                const float* W2 = which ? Wq2 : Wp2;
                u64 am = 0, asd = 0;
                #pragma unroll
                for (int q = 0; q < 4; ++q) {
                    float4 xf = __ldcg((const float4*)(h + lane * 16 + q * 4));
                    ull2 x = *(ull2*)&xf;
                    ull2 u = *(const ull2*)(W2 + (size_t)s * 512 + lane * 16 + q * 4);
                    ull2 v = *(const ull2*)(W2 + (size_t)(s + 32) * 512 + lane * 16 + q * 4);
                    am  = fma2(u.x, x.x, am);  am  = fma2(u.y, x.y, am);
                    asd = fma2(v.x, x.x, asd); asd = fma2(v.y, x.y, asd);
                }
                float sm = hsum(am), ss = hsum(asd);
                #pragma unroll
                for (int o = 16; o; o >>= 1) {
                    sm += __shfl_xor_sync(0xffffffffu, sm, o);
                    ss += __shfl_xor_sync(0xffffffffu, ss, o);
                }
                if (lane == 0) {
                    const float* b2 = which ? bq2 : bp2;
                    float mean = sm + b2[s];
                    float stdv = softplusf(ss + b2[s + 32]) + 1e-5f;
                    const float* nz = which ? nzq : nzp;
                    float e  = nz[((size_t)bb * 256 + t) * 32 + s];
                    float st = mean + stdv * e;
                    size_t base = ((size_t)bb * 256 + t) * 1216 + 1024 + which * 96;
                    out[base + s]      = mean;
                    out[base + 32 + s] = stdv;
                    out[base + 64 + s] = st;
                    if (which) g_stoch[bb * 32 + s] = st;
                }
            }
        }
        gbar();
    }
}

extern "C" void kernel_launch(void* const* d_in, const int* in_sizes, int n_in,
                              void* d_out, int out_size) {
    (void)in_sizes; (void)n_in; (void)out_size;
    cudaFuncSetAttribute((const void*)obsq_kernel,
                         cudaFuncAttributeMaxDynamicSharedMemorySize, 50176);
    cudaFuncSetAttribute((const void*)rssm_kernel,
                         cudaFuncAttributeMaxDynamicSharedMemorySize, SMEM_BYTES);
    obsq_kernel<<<1024, 256, 50176>>>(
        (const float*)d_in[0], (const float*)d_in[14], (const float*)d_in[15]);
    rssm_kernel<<<NCTA, NTHR, SMEM_BYTES>>>(
        (const float*)d_in[0],  (const float*)d_in[1],
        (const float*)d_in[2],  (const float*)d_in[3],
        (const float*)d_in[4],  (const float*)d_in[5],
        (const float*)d_in[6],  (const float*)d_in[7],
        (const float*)d_in[8],  (const float*)d_in[9],
        (const float*)d_in[10], (const float*)d_in[11],
        (const float*)d_in[12], (const float*)d_in[13],
        (const float*)d_in[14], (const float*)d_in[15],
        (const float*)d_in[16], (const float*)d_in[17],
        (float*)d_out);
}

// round 9
// speedup vs baseline: 1.6030x; 1.0015x over previous
#include <cuda_runtime.h>
#include <math.h>

#define NCTA 128
#define NTHR 512

// smem (float4 units):
//   wG   [0, 12336)        : 48 gatecols x 257 (GRU weights, resident)
//   xb   [12336, 14384)    : 2 x 1024 chunk buffers (GRU: e 512 + d 512)
//     ph3 overlay: per buf [0..512) x-chunk, [512..584) w-chunk (8x9)
//     ph1 overlay: scratch 64x25 = 1600 f4; wSa 8x25 = 200 f4 at +1600
#define WG_F4   12336
#define SMEM_F4 (WG_F4 + 2048)
#define SMEM_BYTES (SMEM_F4 * 16)   // 230144 <= 232448

typedef unsigned long long u64;
typedef ulonglong2 ull2;

__device__ __forceinline__ u64 fma2(u64 a, u64 b, u64 c) {
    u64 d;
    asm("fma.rn.f32x2 %0, %1, %2, %3;" : "=l"(d) : "l"(a), "l"(b), "l"(c));
    return d;
}
__device__ __forceinline__ float hsum(u64 v) {
    union { u64 u; float f[2]; } x; x.u = v;
    return x.f[0] + x.f[1];
}
__device__ __forceinline__ float sigm(float x) { return 1.f / (1.f + expf(-x)); }
__device__ __forceinline__ float softplusf(float x) {
    return fmaxf(x, 0.f) + log1pf(expf(-fabsf(x)));
}
__device__ __forceinline__ void cpa16(float4* dst, const void* src) {
    unsigned s = (unsigned)__cvta_generic_to_shared(dst);
    asm volatile("cp.async.cg.shared.global [%0], [%1], 16;" :: "r"(s), "l"(src));
}
#define CP_COMMIT() asm volatile("cp.async.commit_group;" ::: "memory")
#define CP_WAIT1()  asm volatile("cp.async.wait_group 1;" ::: "memory")
#define CP_WAIT0()  asm volatile("cp.async.wait_group 0;" ::: "memory")

// ---------------- persistent state ----------------
__device__ float g_emb[64 * 1024];
__device__ float g_det[2][64 * 1024];
__device__ float g_h1[64 * 512];
__device__ float g_hq[64 * 512];
__device__ float g_stoch[64 * 32];
__device__ float g_obsq[64 * 256 * 512];
__device__ unsigned g_cnt;
__device__ volatile unsigned g_gen;

// grid barrier: fence only in thread0 (cumulative), 128 co-resident CTAs
__device__ __forceinline__ void gbar() {
    __syncthreads();
    if (threadIdx.x == 0) {
        __threadfence();
        unsigned gen = g_gen;
        if (atomicAdd(&g_cnt, 1u) == NCTA - 1) {
            g_cnt = 0;
            __threadfence();
            g_gen = gen + 1;
        } else {
            while (g_gen == gen) { }
        }
        __threadfence();
    }
    __syncthreads();
}

// ======== pre-pass: g_obsq[r][c] = obs[r]·Wq1[c][1024:] + bq1[c] ========
__global__ void __launch_bounds__(256)
obsq_kernel(const float* __restrict__ obs, const float* __restrict__ Wq1,
            const float* __restrict__ bq1) {
    extern __shared__ float4 S[];
    const int tid = threadIdx.x, lane = tid & 31, wrp = tid >> 5;
    const int rt = blockIdx.x >> 2, ct = blockIdx.x & 3;
    const int r0 = rt * 64, c0 = ct * 128;
    const int rh = wrp >> 2, cgq = wrp & 3;

    u64 acc[32];
    #pragma unroll
    for (int j = 0; j < 32; ++j) acc[j] = 0ull;

    for (int c = 0; c < 16; ++c) {
        for (int i = tid; i < 1024; i += 256) {
            int row = i >> 4, k4 = i & 15;
            S[row * 17 + k4] = *(const float4*)(obs + (size_t)(r0 + row) * 1024 + c * 64 + k4 * 4);
        }
        for (int i = tid; i < 2048; i += 256) {
            int col = i >> 4, k4 = i & 15;
            S[1088 + col * 16 + k4] =
                *(const float4*)(Wq1 + (size_t)(c0 + col) * 2048 + 1024 + c * 64 + k4 * 4);
        }
        __syncthreads();
        const ull2* xr = (const ull2*)(S + (rh * 32 + lane) * 17);
        const ull2* wb = (const ull2*)(S + 1088 + (cgq * 32) * 16);
        for (int k4 = 0; k4 < 16; ++k4) {
            ull2 x = xr[k4];
            #pragma unroll
            for (int j = 0; j < 32; ++j) {
                ull2 w = wb[j * 16 + k4];
                acc[j] = fma2(w.x, x.x, acc[j]);
                acc[j] = fma2(w.y, x.y, acc[j]);
            }
        }
        __syncthreads();
    }
    int r = r0 + rh * 32 + lane;
    #pragma unroll
    for (int j = 0; j < 32; ++j) {
        int col = c0 + cgq * 32 + j;
        g_obsq[(size_t)r * 512 + col] = hsum(acc[j]) + bq1[col];
    }
}

// ======== persistent rollout ========
__global__ void __launch_bounds__(NTHR, 1)
rssm_kernel(const float* __restrict__ obs,   const float* __restrict__ act,
            const float* __restrict__ nzp,   const float* __restrict__ nzq,
            const float* __restrict__ Wsa, const float* __restrict__ bsa,
            const float* __restrict__ Wih, const float* __restrict__ bih,
            const float* __restrict__ Whh, const float* __restrict__ bhh,
            const float* __restrict__ Wp1, const float* __restrict__ bp1,
            const float* __restrict__ Wp2, const float* __restrict__ bp2,
            const float* __restrict__ Wq1, const float* __restrict__ bq1,
            const float* __restrict__ Wq2, const float* __restrict__ bq2,
            float* __restrict__ out)
{
    extern __shared__ float4 S[];
    float4* wG = S;
    float4* xb = S + WG_F4;

    const int tid  = threadIdx.x;
    const int lane = tid & 31;
    const int wrp  = tid >> 5;
    const int c0g  = blockIdx.x * 8;

    // GRU tiling ids: warp = 16 rows x 2 cols; thread = 2 rows x 3 gates (one matrix)
    const int gw_r = wrp & 3;             // row group (16 rows)
    const int gw_c = wrp >> 2;            // col group (2 cols)
    const int tr   = lane & 7;
    const int tc   = lane >> 3;           // 0..3
    const int gr0  = gw_r * 16 + tr;      // row 0
    const int gr1  = gr0 + 8;             // row 1
    const int gcol = gw_c * 2 + (tc >> 1);           // 0..7 within CTA
    const int gpar = (tc & 1);                        // 0 = i-gates (emb), 1 = h-gates (det)
    // ph3/ph1 tiling: warp = 8 rows x 4 cols; thread = 1 output
    const int pr   = (wrp & 7) * 8 + (lane & 7);      // row 0..63
    const int pc   = (wrp >> 3) * 4 + (lane >> 3);    // col 0..7

    // ---- init: zero state, load GRU weights into smem [gc][257] ----
    for (int i = blockIdx.x * NTHR + tid; i < 64 * 1024; i += NCTA * NTHR)
        g_det[0][i] = 0.f;
    for (int i = blockIdx.x * NTHR + tid; i < 64 * 32; i += NCTA * NTHR)
        g_stoch[i] = 0.f;
    for (int i = tid; i < WG_F4; i += NTHR) {
        int gc = i / 257, k = i - gc * 257;
        if (k < 256) {
            int col = gc / 6, g = gc - col * 6;
            const float* srow = (g < 3)
                ? (Wih + ((size_t)(c0g + col) + 1024 * g) * 1024)
                : (Whh + ((size_t)(c0g + col) + 1024 * (g - 3)) * 1024);
            wG[i] = *(const float4*)(srow + k * 4);
        }
    }
    gbar();

    // GRU per-thread weight bases: 3 gates at gc = gcol*6 + gpar*3 + {0,1,2}
    const float4* wg0 = wG + (gcol * 6 + gpar * 3 + 0) * 257;
    const float4* wg1 = wG + (gcol * 6 + gpar * 3 + 1) * 257;
    const float4* wg2 = wG + (gcol * 6 + gpar * 3 + 2) * 257;

    for (int t = 0; t < 256; ++t) {
        const int p = t & 1;
        const float* detP = g_det[p];
        float*       detN = g_det[p ^ 1];

        // ===== phase 1: emb = relu([stoch|act] @ Wsa^T + bsa) =====
        {
            float4* scr = xb;            // 64 x 25
            float4* wsa = xb + 1600;     // 8 x 25
            for (int i = tid; i < 1536; i += NTHR) {
                int row = i / 24, k4 = i - row * 24;
                const void* src = (k4 < 8)
                    ? (const void*)(g_stoch + row * 32 + k4 * 4)
                    : (const void*)(act + ((size_t)row * 256 + t) * 64 + (k4 - 8) * 4);
                cpa16(scr + row * 25 + k4, src);
            }
            if (tid < 192) {
                int c = tid / 24, k4 = tid - c * 24;
                cpa16(wsa + c * 25 + k4, Wsa + (size_t)(c0g + c) * 96 + k4 * 4);
            }
            CP_COMMIT(); CP_WAIT0();
            __syncthreads();
            u64 a = 0;
            #pragma unroll 6
            for (int k4 = 0; k4 < 24; ++k4) {
                ull2 x = *(const ull2*)(scr + pr * 25 + k4);
                ull2 w = *(const ull2*)(wsa + pc * 25 + k4);
                a = fma2(w.x, x.x, a); a = fma2(w.y, x.y, a);
            }
            g_emb[(size_t)pr * 1024 + c0g + pc] = fmaxf(hsum(a) + bsa[c0g + pc], 0.f);
        }
        gbar();

        // ===== phase 2: GRU =====
        {
            float4* b0 = xb;
            float4* b1 = xb + 1024;
            u64 acc[6] = {0, 0, 0, 0, 0, 0};   // [r01*3 + gate]

            auto stageG = [&](float4* buf, int j) {
                #pragma unroll
                for (int s = 0; s < 2; ++s) {
                    int i = tid + s * 512;
                    int mat = i >> 9, idx = i & 511, row = idx >> 3, k4 = idx & 7;
                    const float* src = (mat ? detP : g_emb)
                        + (size_t)row * 1024 + j * 32 + k4 * 4;
                    cpa16(buf + mat * 512 + row * 8 + (k4 ^ (row & 7)), src);
                }
            };
            stageG(b0, 0); CP_COMMIT();
            stageG(b1, 1); CP_COMMIT();

            const int xbase0 = gpar * 512 + gr0 * 8;
            const int xbase1 = gpar * 512 + gr1 * 8;
            for (int j = 0; j < 32; ++j) {
                if (j == 31) CP_WAIT0(); else CP_WAIT1();
                __syncthreads();
                const float4* buf = (j & 1) ? b1 : b0;
                const float4* w0 = wg0 + j * 8;
                const float4* w1 = wg1 + j * 8;
                const float4* w2 = wg2 + j * 8;
                #pragma unroll
                for (int k4 = 0; k4 < 8; ++k4) {
                    int sk = k4 ^ tr;
                    ull2 x0 = *(const ull2*)(buf + xbase0 + sk);
                    ull2 x1 = *(const ull2*)(buf + xbase1 + sk);
                    ull2 wa = *(const ull2*)(w0 + k4);
                    ull2 wb = *(const ull2*)(w1 + k4);
                    ull2 wc = *(const ull2*)(w2 + k4);
                    acc[0] = fma2(wa.x, x0.x, acc[0]); acc[0] = fma2(wa.y, x0.y, acc[0]);
                    acc[1] = fma2(wb.x, x0.x, acc[1]); acc[1] = fma2(wb.y, x0.y, acc[1]);
                    acc[2] = fma2(wc.x, x0.x, acc[2]); acc[2] = fma2(wc.y, x0.y, acc[2]);
                    acc[3] = fma2(wa.x, x1.x, acc[3]); acc[3] = fma2(wa.y, x1.y, acc[3]);
                    acc[4] = fma2(wb.x, x1.x, acc[4]); acc[4] = fma2(wb.y, x1.y, acc[4]);
                    acc[5] = fma2(wc.x, x1.x, acc[5]); acc[5] = fma2(wc.y, x1.y, acc[5]);
                }
                __syncthreads();
                if (j < 30) { stageG((j & 1) ? b1 : b0, j + 2); CP_COMMIT(); }
            }

            const int col = c0g + gcol;
            const float* bb = gpar ? bhh : bih;
            float s[6];
            #pragma unroll
            for (int r01 = 0; r01 < 2; ++r01)
                #pragma unroll
                for (int m = 0; m < 3; ++m)
                    s[r01 * 3 + m] = hsum(acc[r01 * 3 + m]) + bb[col + 1024 * m];
            float o[6];
            #pragma unroll
            for (int i = 0; i < 6; ++i)
                o[i] = __shfl_xor_sync(0xffffffffu, s[i], 8);
            if (!gpar) {
                #pragma unroll
                for (int r01 = 0; r01 < 2; ++r01) {
                    int row = r01 ? gr1 : gr0;
                    float r  = sigm(s[r01 * 3 + 0] + o[r01 * 3 + 0]);
                    float z  = sigm(s[r01 * 3 + 1] + o[r01 * 3 + 1]);
                    float n  = tanhf(s[r01 * 3 + 2] + r * o[r01 * 3 + 2]);
                    float hp = detP[(size_t)row * 1024 + col];
                    float hw = (1.f - z) * n + z * hp;
                    detN[(size_t)row * 1024 + col] = hw;
                    out[((size_t)row * 256 + t) * 1216 + col] = hw;
                }
            }
        }
        gbar();

        // ===== phase 3: h1 / hq first layers (K=1024 both; obs part precomputed) =====
        {
            const bool isQ = blockIdx.x & 1;
            const int  c0  = (blockIdx.x >> 1) * 8;
            const float* W1 = isQ ? Wq1 : Wp1;
            const size_t K1 = isQ ? 2048 : 1024;
            float4* b0 = xb;
            float4* b1 = xb + 1024;
            u64 a = 0;

            auto stage3 = [&](float4* buf, int j) {
                {
                    int row = tid >> 3, k4 = tid & 7;
                    if (tid < 512)
                        cpa16(buf + row * 8 + (k4 ^ (row & 7)),
                              detN + (size_t)row * 1024 + j * 32 + k4 * 4);
                }
                if (tid < 64) {
                    int c = tid >> 3, k4 = tid & 7;
                    cpa16(buf + 512 + c * 9 + k4,
                          W1 + (size_t)(c0 + c) * K1 + j * 32 + k4 * 4);
                }
            };
            stage3(b0, 0); CP_COMMIT();
            stage3(b1, 1); CP_COMMIT();

            for (int j = 0; j < 32; ++j) {
                if (j == 31) CP_WAIT0(); else CP_WAIT1();
                __syncthreads();
                const float4* buf = (j & 1) ? b1 : b0;
                #pragma unroll
                for (int k4 = 0; k4 < 8; ++k4) {
                    ull2 x = *(const ull2*)(buf + pr * 8 + (k4 ^ (pr & 7)));
                    ull2 w = *(const ull2*)(buf + 512 + pc * 9 + k4);
                    a = fma2(w.x, x.x, a); a = fma2(w.y, x.y, a);
                }
                __syncthreads();
                if (j < 30) { stage3((j & 1) ? b1 : b0, j + 2); CP_COMMIT(); }
            }

            const int col = c0 + pc;
            float base = isQ ? g_obsq[((size_t)pr * 256 + t) * 512 + col] : bp1[col];
            float v = fmaxf(hsum(a) + base, 0.f);
            (isQ ? g_hq : g_h1)[(size_t)pr * 512 + col] = v;
        }
        gbar();

        // ===== phase 4: second-layer heads, stochastic state =====
        {
            const int gw = blockIdx.x * 16 + wrp;       // 0..2047
            #pragma unroll
            for (int i = 0; i < 2; ++i) {
                int pi    = gw * 2 + i;                 // 0..4095
                int which = pi & 1;
                int s     = (pi >> 1) & 31;
                int bb    = pi >> 6;
                const float* h  = (which ? g_hq : g_h1) + (size_t)bb * 512;
                const float* W2 = which ? Wq2 : Wp2;
                u64 am = 0, asd = 0;
                #pragma unroll
                for (int q = 0; q < 4; ++q) {
                    float4 xf = __ldcg((const float4*)(h + lane * 16 + q * 4));
                    ull2 x = *(ull2*)&xf;
                    ull2 u = *(const ull2*)(W2 + (size_t)s * 512 + lane * 16 + q * 4);
                    ull2 v = *(const ull2*)(W2 + (size_t)(s + 32) * 512 + lane * 16 + q * 4);
                    am  = fma2(u.x, x.x, am);  am  = fma2(u.y, x.y, am);
                    asd = fma2(v.x, x.x, asd); asd = fma2(v.y, x.y, asd);
                }
                float sm = hsum(am), ss = hsum(asd);
                #pragma unroll
                for (int o = 16; o; o >>= 1) {
                    sm += __shfl_xor_sync(0xffffffffu, sm, o);
                    ss += __shfl_xor_sync(0xffffffffu, ss, o);
                }
                if (lane == 0) {
                    const float* b2 = which ? bq2 : bp2;
                    float mean = sm + b2[s];
                    float stdv = softplusf(ss + b2[s + 32]) + 1e-5f;
                    const float* nz = which ? nzq : nzp;
                    float e  = nz[((size_t)bb * 256 + t) * 32 + s];
                    float st = mean + stdv * e;
                    size_t base = ((size_t)bb * 256 + t) * 1216 + 1024 + which * 96;
                    out[base + s]      = mean;
                    out[base + 32 + s] = stdv;
                    out[base + 64 + s] = st;
                    if (which) g_stoch[bb * 32 + s] = st;
                }
            }
        }
        gbar();
    }
}

extern "C" void kernel_launch(void* const* d_in, const int* in_sizes, int n_in,
                              void* d_out, int out_size) {
    (void)in_sizes; (void)n_in; (void)out_size;
    cudaFuncSetAttribute((const void*)obsq_kernel,
                         cudaFuncAttributeMaxDynamicSharedMemorySize, 50176);
    cudaFuncSetAttribute((const void*)rssm_kernel,
                         cudaFuncAttributeMaxDynamicSharedMemorySize, SMEM_BYTES);
    obsq_kernel<<<1024, 256, 50176>>>(
        (const float*)d_in[0], (const float*)d_in[14], (const float*)d_in[15]);
    rssm_kernel<<<NCTA, NTHR, SMEM_BYTES>>>(
        (const float*)d_in[0],  (const float*)d_in[1],
        (const float*)d_in[2],  (const float*)d_in[3],
        (const float*)d_in[4],  (const float*)d_in[5],
        (const float*)d_in[6],  (const float*)d_in[7],
        (const float*)d_in[8],  (const float*)d_in[9],
        (const float*)d_in[10], (const float*)d_in[11],
        (const float*)d_in[12], (const float*)d_in[13],
        (const float*)d_in[14], (const float*)d_in[15],
        (const float*)d_in[16], (const float*)d_in[17],
        (float*)d_out);
}